// round 13
// baseline (speedup 1.0000x reference)
#include <cuda_runtime.h>

#define L_   9
#define C_   256
#define K_   3
#define V_   25
#define VP_  32
#define G_   9
#define T_   128
#define NC_  60
#define CIN_ 3
#define GH_  4
#define CV_  (C_*V_)    /* 6400 */
#define CVP_ (C_*VP_)   /* 8192 */

// ---------------- scratch (device globals; zero-initialized at load) --------
__device__ __align__(16) float g_hl[L_+1][T_][CVP_];  // per-layer inputs (pads stay 0)
__device__ __align__(16) float g_anl[L_][T_][CVP_];   // relu(LN1(z)) per layer (pads stay 0)
__device__ __align__(16) float g_aneg[L_][CVP_];      // relu(LN1(zero frame)) per layer
__device__ __align__(16) float g_WgT[L_][K_][C_][C_]; // [l][k][ci][co]
__device__ __align__(16) float g_WtT[L_][G_][C_][C_]; // [l][g][ci][o]
__device__ int g_fg[L_][T_];                          // gcn(l,t) done
__device__ int g_fh[L_+1][T_];                        // h input of layer l at t ready

// ---------------- prep kernels ------------------------------------------------
__global__ void k_zero_flags() {
    int i = blockIdx.x * blockDim.x + threadIdx.x;
    if (i < L_ * T_) (&g_fg[0][0])[i] = 0;
    if (i < (L_ + 1) * T_) (&g_fh[0][0])[i] = 0;
}

__global__ void k_prep_wg(const float* __restrict__ Wg) {
    int idx = blockIdx.x * blockDim.x + threadIdx.x;
    if (idx >= L_ * K_ * C_ * C_) return;
    int ci = idx % C_; int r = idx / C_;
    int co = r % C_;   r /= C_;
    int k  = r % K_;   int l = r / K_;
    g_WgT[l][k][ci][co] = Wg[((size_t)(l * K_ * C_ + k * C_ + co)) * C_ + ci];
}

__global__ void k_prep_wt(const float* __restrict__ Wt) {
    int idx = blockIdx.x * blockDim.x + threadIdx.x;
    if (idx >= L_ * C_ * C_) return;
    int c = idx % C_; int r = idx / C_;
    int o = r % C_;   int l = r / C_;
    const float* src = Wt + (((size_t)(l * C_ + o)) * C_ + c) * G_;  // 9 consecutive
    #pragma unroll
    for (int g = 0; g < G_; g++) g_WtT[l][g][c][o] = src[g];
}

__global__ void k_prep_aneg(const float* __restrict__ ln1_b) {
    int idx = blockIdx.x * blockDim.x + threadIdx.x;
    if (idx >= L_ * CVP_) return;
    int e = idx % CVP_, l = idx / CVP_;
    int c = e >> 5, v = e & 31;
    float r = 0.f;
    if (v < V_) r = fmaxf(ln1_b[(l * C_ + c) * V_ + v], 0.f);
    g_aneg[l][e] = r;
}

// ---------------- fused network kernel ---------------------------------------
// smem layout (floats): h_s/a_s[8192] | hA_s[24576] | Al_s[1875] | rsum[75] | red[66]
#define SMEM_FLOATS (CVP_ + K_*CVP_ + K_*V_*V_ + K_*V_ + 66)

__global__ __launch_bounds__(1024, 1)
void k_main(const float* __restrict__ x,
            const float* __restrict__ A,
            const float* __restrict__ ln_in_w,
            const float* __restrict__ ln_in_b,
            const float* __restrict__ W_in,
            const float* __restrict__ b_in,
            const float* __restrict__ bg,
            const float* __restrict__ ln1_w,
            const float* __restrict__ ln1_b,
            const float* __restrict__ bt,
            const float* __restrict__ ln2_w,
            const float* __restrict__ ln2_b,
            const float* __restrict__ imp,
            const float* __restrict__ W_out,
            const float* __restrict__ b_out,
            float* __restrict__ out)
{
    extern __shared__ __align__(16) float sm[];
    float* h_s  = sm;                          // 8192 (also tcn a_s)
    float* hA_s = sm + CVP_;                   // 24576
    float* Al_s = sm + CVP_ + K_*CVP_;         // 1875
    float* rsum = Al_s + K_*V_*V_;             // 75
    float* red  = rsum + K_*V_;                // 66

    int t = blockIdx.x, tid = threadIdx.x;     // 1024 threads
    int wid = tid >> 5, lane = tid & 31;

    // ======================= input stage =======================
    {
        float xv = 0.f, s = 0.f, ss = 0.f;
        if (tid < CIN_ * V_) {
            int ci = tid / V_, v = tid % V_;
            xv = x[(size_t)ci * T_ * V_ + (size_t)t * V_ + v];
            s = xv; ss = xv * xv;
        }
        #pragma unroll
        for (int o = 16; o; o >>= 1) {
            s  += __shfl_xor_sync(0xffffffffu, s, o);
            ss += __shfl_xor_sync(0xffffffffu, ss, o);
        }
        if (lane == 0) { red[wid] = s; red[32 + wid] = ss; }
        __syncthreads();
        if (tid == 0) {
            float S = 0.f, SS = 0.f;
            #pragma unroll
            for (int i = 0; i < 32; i++) { S += red[i]; SS += red[32 + i]; }
            float m = S / (CIN_ * V_);
            red[64] = m;
            red[65] = rsqrtf(SS / (CIN_ * V_) - m * m + 1e-5f);
        }
        __syncthreads();
        float m = red[64], rs = red[65];
        if (tid < CIN_ * V_) hA_s[tid] = (xv - m) * rs * ln_in_w[tid] + ln_in_b[tid];
        __syncthreads();

        float* outp = g_hl[0][t];
        for (int e = tid; e < CVP_; e += 1024) {
            int c = e >> 5, v = e & 31;
            float a = 0.f;
            if (v < V_) {
                a = b_in[c];
                #pragma unroll
                for (int ci = 0; ci < CIN_; ci++)
                    a = fmaf(W_in[c * CIN_ + ci], hA_s[ci * V_ + v], a);
            }
            outp[e] = a;
        }
        __threadfence();
        __syncthreads();
        if (tid == 0) atomicExch(&g_fh[0][t], 1);
    }

    // ======================= layers =======================
    for (int l = 0; l < L_; l++) {
        // ---------------- GCN ----------------
        {
            const float4* src = (const float4*)g_hl[l][t];
            float4* dst = (float4*)h_s;
            #pragma unroll
            for (int i = 0; i < 2; i++) dst[tid + i * 1024] = src[tid + i * 1024];
        }
        for (int i = tid; i < K_ * V_ * V_; i += 1024)
            Al_s[i] = A[i] * imp[l * K_ * V_ * V_ + i];
        __syncthreads();

        for (int i = tid; i < K_ * V_; i += 1024) {
            int k = i / V_, w = i % V_;
            float s = 0.f;
            #pragma unroll
            for (int v = 0; v < V_; v++) s += Al_s[k * V_ * V_ + v * V_ + w];
            rsum[i] = s;
        }
        for (int e = tid; e < K_ * CV_; e += 1024) {
            int k = e / CV_, r = e % CV_, c = r / V_, w = r % V_;
            const float* hr = h_s + (c << 5);
            const float* ar = Al_s + k * V_ * V_ + w;
            float s = 0.f;
            #pragma unroll
            for (int v = 0; v < V_; v++) s = fmaf(hr[v], ar[v * V_], s);
            hA_s[k * CVP_ + (c << 5) + w] = s;
        }
        __syncthreads();

        int c = tid & 255, vg = tid >> 8;
        {
            float acc[8];
            float s = 0.f, ss = 0.f;
            float bg0 = bg[l * K_ * C_ + c];
            float bg1 = bg[l * K_ * C_ + C_ + c];
            float bg2 = bg[l * K_ * C_ + 2 * C_ + c];

            if (vg < 3) {
                int vb = vg << 3;
                #pragma unroll
                for (int j = 0; j < 8; j++) {
                    int w = vb + j;
                    acc[j] = bg0 * rsum[w] + bg1 * rsum[V_ + w] + bg2 * rsum[2 * V_ + w];
                }
                #pragma unroll
                for (int k = 0; k < K_; k++) {
                    const float* wg = &g_WgT[l][k][0][c];
                    const float* ap = hA_s + k * CVP_ + vb;
                    #pragma unroll 4
                    for (int ci = 0; ci < C_; ci++) {
                        float wv = wg[ci * C_];
                        float4 h0 = *(const float4*)(ap + (ci << 5));
                        float4 h1 = *(const float4*)(ap + (ci << 5) + 4);
                        acc[0] = fmaf(wv, h0.x, acc[0]);
                        acc[1] = fmaf(wv, h0.y, acc[1]);
                        acc[2] = fmaf(wv, h0.z, acc[2]);
                        acc[3] = fmaf(wv, h0.w, acc[3]);
                        acc[4] = fmaf(wv, h1.x, acc[4]);
                        acc[5] = fmaf(wv, h1.y, acc[5]);
                        acc[6] = fmaf(wv, h1.z, acc[6]);
                        acc[7] = fmaf(wv, h1.w, acc[7]);
                    }
                }
                #pragma unroll
                for (int j = 0; j < 8; j++) { s += acc[j]; ss += acc[j] * acc[j]; }
            } else {
                acc[0] = bg0 * rsum[24] + bg1 * rsum[V_ + 24] + bg2 * rsum[2 * V_ + 24];
                #pragma unroll
                for (int k = 0; k < K_; k++) {
                    const float* wg = &g_WgT[l][k][0][c];
                    const float* ap = hA_s + k * CVP_ + 24;
                    #pragma unroll 4
                    for (int ci = 0; ci < C_; ci++)
                        acc[0] = fmaf(wg[ci * C_], ap[ci << 5], acc[0]);
                }
                s = acc[0]; ss = acc[0] * acc[0];
            }

            #pragma unroll
            for (int o = 16; o; o >>= 1) {
                s  += __shfl_xor_sync(0xffffffffu, s, o);
                ss += __shfl_xor_sync(0xffffffffu, ss, o);
            }
            if (lane == 0) { red[wid] = s; red[32 + wid] = ss; }
            __syncthreads();
            if (tid < 32) {
                float S = red[tid], SS = red[32 + tid];
                #pragma unroll
                for (int o = 16; o; o >>= 1) {
                    S  += __shfl_xor_sync(0xffffffffu, S, o);
                    SS += __shfl_xor_sync(0xffffffffu, SS, o);
                }
                if (tid == 0) {
                    float m = S / CV_;
                    red[64] = m;
                    red[65] = rsqrtf(SS / CV_ - m * m + 1e-5f);
                }
            }
            __syncthreads();
            float m = red[64], rs = red[65];

            const float* w1 = ln1_w + (l * C_ + c) * V_;
            const float* b1 = ln1_b + (l * C_ + c) * V_;
            float* outp = g_anl[l][t] + (c << 5);
            if (vg < 3) {
                int vb = vg << 3;
                #pragma unroll
                for (int j = 0; j < 8; j++) {
                    int v = vb + j;
                    outp[v] = fmaxf(fmaf((acc[j] - m) * rs, w1[v], b1[v]), 0.f);
                }
            } else {
                outp[24] = fmaxf(fmaf((acc[0] - m) * rs, w1[24], b1[24]), 0.f);
            }
        }
        __threadfence();
        __syncthreads();
        if (tid == 0) atomicExch(&g_fg[l][t], 1);

        // ---------------- TCN ----------------
        if (tid == 0) {
            int tmin = t - (G_ - 1); if (tmin < 0) tmin = 0;
            for (int tau = tmin; tau < t; tau++)
                while (*(volatile int*)&g_fg[l][tau] == 0) __nanosleep(64);
            if (t >= GH_)
                while (*(volatile int*)&g_fh[l][t - GH_] == 0) __nanosleep(64);
            __threadfence();
        }
        __syncthreads();

        {
            int o = tid & 255;
            int vb = vg << 3;   // meaningful for vg<3
            float acc[8];
            float btv = bt[l * C_ + o];
            #pragma unroll
            for (int j = 0; j < 8; j++) acc[j] = btv;

            for (int g = 0; g < G_; g++) {
                __syncthreads();
                int tau = t - g;
                const float4* src = (const float4*)((tau >= 0) ? g_anl[l][tau] : g_aneg[l]);
                float4* dst = (float4*)h_s;
                #pragma unroll
                for (int i = 0; i < 2; i++) dst[tid + i * 1024] = src[tid + i * 1024];
                __syncthreads();

                const float* wt = &g_WtT[l][g][0][o];
                if (vg < 3) {
                    const float* ap = h_s + vb;
                    #pragma unroll 4
                    for (int ci = 0; ci < C_; ci++) {
                        float wv = wt[ci * C_];
                        float4 a0 = *(const float4*)(ap + (ci << 5));
                        float4 a1 = *(const float4*)(ap + (ci << 5) + 4);
                        acc[0] = fmaf(wv, a0.x, acc[0]);
                        acc[1] = fmaf(wv, a0.y, acc[1]);
                        acc[2] = fmaf(wv, a0.z, acc[2]);
                        acc[3] = fmaf(wv, a0.w, acc[3]);
                        acc[4] = fmaf(wv, a1.x, acc[4]);
                        acc[5] = fmaf(wv, a1.y, acc[5]);
                        acc[6] = fmaf(wv, a1.z, acc[6]);
                        acc[7] = fmaf(wv, a1.w, acc[7]);
                    }
                } else {
                    const float* ap = h_s + 24;
                    #pragma unroll 4
                    for (int ci = 0; ci < C_; ci++)
                        acc[0] = fmaf(wt[ci * C_], ap[ci << 5], acc[0]);
                }
            }

            float s = 0.f, ss = 0.f;
            if (vg < 3) {
                #pragma unroll
                for (int j = 0; j < 8; j++) { s += acc[j]; ss += acc[j] * acc[j]; }
            } else {
                s = acc[0]; ss = acc[0] * acc[0];
            }
            #pragma unroll
            for (int off = 16; off; off >>= 1) {
                s  += __shfl_xor_sync(0xffffffffu, s, off);
                ss += __shfl_xor_sync(0xffffffffu, ss, off);
            }
            if (lane == 0) { red[wid] = s; red[32 + wid] = ss; }
            __syncthreads();
            if (tid < 32) {
                float S = red[tid], SS = red[32 + tid];
                #pragma unroll
                for (int off = 16; off; off >>= 1) {
                    S  += __shfl_xor_sync(0xffffffffu, S, off);
                    SS += __shfl_xor_sync(0xffffffffu, SS, off);
                }
                if (tid == 0) {
                    float m = S / CV_;
                    red[64] = m;
                    red[65] = rsqrtf(SS / CV_ - m * m + 1e-5f);
                }
            }
            __syncthreads();
            float m = red[64], rs = red[65];

            const float* resp = (t >= GH_) ? (g_hl[l][t - GH_] + (o << 5)) : nullptr;
            float* outp = g_hl[l + 1][t] + (o << 5);
            const float* w2 = ln2_w + (l * C_ + o) * V_;
            const float* b2 = ln2_b + (l * C_ + o) * V_;
            if (vg < 3) {
                #pragma unroll
                for (int j = 0; j < 8; j++) {
                    int v = vb + j;
                    float res = resp ? resp[v] : 0.f;
                    outp[v] = fmaxf(fmaf((acc[j] - m) * rs, w2[v], b2[v]) + res, 0.f);
                }
            } else {
                float res = resp ? resp[24] : 0.f;
                outp[24] = fmaxf(fmaf((acc[0] - m) * rs, w2[24], b2[24]) + res, 0.f);
            }
        }
        __threadfence();
        __syncthreads();
        if (tid == 0) atomicExch(&g_fh[l + 1][t], 1);
    }

    // ======================= head =======================
    __syncthreads();
    {
        const float* h = g_hl[L_][t];
        if (tid < 256) {
            float s = 0.f;
            #pragma unroll
            for (int v = 0; v < V_; v++) s += h[(tid << 5) + v];
            sm[tid] = s * (1.f / V_);
        }
        __syncthreads();
        if (tid < NC_) {
            float a = b_out[tid];
            #pragma unroll 8
            for (int c2 = 0; c2 < C_; c2++) a = fmaf(W_out[tid * C_ + c2], sm[c2], a);
            out[t * NC_ + tid] = a;
        }
    }
}

// ---------------- launch ------------------------------------------------------
extern "C" void kernel_launch(void* const* d_in, const int* in_sizes, int n_in,
                              void* d_out, int out_size) {
    const float* x       = (const float*)d_in[0];
    const float* A       = (const float*)d_in[1];
    const float* ln_in_w = (const float*)d_in[2];
    const float* ln_in_b = (const float*)d_in[3];
    const float* W_in    = (const float*)d_in[4];
    const float* b_in    = (const float*)d_in[5];
    const float* Wg      = (const float*)d_in[6];
    const float* bg      = (const float*)d_in[7];
    const float* ln1_w   = (const float*)d_in[8];
    const float* ln1_b   = (const float*)d_in[9];
    const float* Wt      = (const float*)d_in[10];
    const float* bt      = (const float*)d_in[11];
    const float* ln2_w   = (const float*)d_in[12];
    const float* ln2_b   = (const float*)d_in[13];
    const float* imp     = (const float*)d_in[14];
    const float* W_out   = (const float*)d_in[15];
    const float* b_out   = (const float*)d_in[16];
    float* out = (float*)d_out;

    int smem = SMEM_FLOATS * (int)sizeof(float);
    cudaFuncSetAttribute(k_main, cudaFuncAttributeMaxDynamicSharedMemorySize, smem);

    k_zero_flags<<<5, 256>>>();
    {
        int n = L_ * K_ * C_ * C_;
        k_prep_wg<<<(n + 255) / 256, 256>>>(Wg);
    }
    {
        int n = L_ * C_ * C_;
        k_prep_wt<<<(n + 255) / 256, 256>>>(Wt);
    }
    {
        int n = L_ * CVP_;
        k_prep_aneg<<<(n + 255) / 256, 256>>>(ln1_b);
    }
    k_main<<<T_, 1024, smem>>>(x, A, ln_in_w, ln_in_b, W_in, b_in, bg,
                               ln1_w, ln1_b, bt, ln2_w, ln2_b, imp,
                               W_out, b_out, out);
}

// round 15
// speedup vs baseline: 1.3368x; 1.3368x over previous
#include <cuda_runtime.h>
#include <cuda_bf16.h>
#include <cstdint>

#define L_   9
#define C_   256
#define K_   3
#define V_   25
#define VP_  32
#define G_   9
#define T_   128
#define NC_  60
#define CIN_ 3
#define GH_  4
#define CV_  (C_*V_)    /* 6400 */
#define CVP_ (C_*VP_)   /* 8192 */

// ---------------- bf16 helpers ----------------------------------------------
__device__ __forceinline__ unsigned short f2bf(float x) {
    return __bfloat16_as_ushort(__float2bfloat16(x));
}
__device__ __forceinline__ float bf2f(unsigned short u) {
    return __bfloat162float(__ushort_as_bfloat16(u));
}

// mma.sync m16n8k16 row.col f32.bf16.bf16.f32
#define MMA16816(d, a, b0, b1) \
    asm volatile("mma.sync.aligned.m16n8k16.row.col.f32.bf16.bf16.f32 " \
        "{%0,%1,%2,%3}, {%4,%5,%6,%7}, {%8,%9}, {%0,%1,%2,%3};" \
        : "+f"((d)[0]), "+f"((d)[1]), "+f"((d)[2]), "+f"((d)[3]) \
        : "r"((a).x), "r"((a).y), "r"((a).z), "r"((a).w), "r"(b0), "r"(b1))

// ---------------- scratch (device globals; zero-initialized at load) --------
__device__ __align__(16) float g_h[2][T_][CVP_];      // padded activations (pads stay 0)
__device__ __align__(16) float g_anorm[T_][CVP_];     // relu(LN1(z)), padded (pads stay 0)
__device__ __align__(16) float g_aneg[L_][CVP_];      // relu(LN1(zero frame)) per layer
__device__ __align__(16) float g_WgT[L_][K_][C_][C_]; // [l][k][ci][co]
// TCN weights pre-packed as mma A-fragments:
// idx = ((((l*9+g)*2+term)*16+mt)*16+kt)*32+lane, uint4 per lane
__device__ __align__(16) uint4 g_WtPk[L_*G_*2*16*16*32];

// ---------------- weight prep ------------------------------------------------
__global__ void k_prep_wg(const float* __restrict__ Wg) {
    int idx = blockIdx.x * blockDim.x + threadIdx.x;
    if (idx >= L_ * K_ * C_ * C_) return;
    int ci = idx % C_; int r = idx / C_;
    int co = r % C_;   r /= C_;
    int k  = r % K_;   int l = r / K_;
    g_WgT[l][k][ci][co] = Wg[((size_t)(l * K_ * C_ + k * C_ + co)) * C_ + ci];
}

__global__ void k_prep_wtpk(const float* __restrict__ Wt) {
    int idx = blockIdx.x * blockDim.x + threadIdx.x;
    if (idx >= L_ * G_ * 2 * 16 * 16 * 32) return;
    int lane = idx & 31;
    int kt   = (idx >> 5) & 15;
    int mt   = (idx >> 9) & 15;
    int term = (idx >> 13) & 1;
    int rem  = idx >> 14;
    int g = rem % G_, l = rem / G_;
    int grp = lane >> 2, tig = lane & 3;
    int m0 = mt * 16 + grp, k0 = kt * 16 + tig * 2;

    auto wv = [&](int m, int k) -> unsigned {
        float w = Wt[(((size_t)(l * C_ + m)) * C_ + k) * G_ + g];
        unsigned short h = f2bf(w);
        if (term == 0) return (unsigned)h;
        return (unsigned)f2bf(w - bf2f(h));
    };
    unsigned a0 = wv(m0,     k0)     | (wv(m0,     k0 + 1) << 16);
    unsigned a1 = wv(m0 + 8, k0)     | (wv(m0 + 8, k0 + 1) << 16);
    unsigned a2 = wv(m0,     k0 + 8) | (wv(m0,     k0 + 9) << 16);
    unsigned a3 = wv(m0 + 8, k0 + 8) | (wv(m0 + 8, k0 + 9) << 16);
    g_WtPk[idx] = make_uint4(a0, a1, a2, a3);
}

__global__ void k_prep_aneg(const float* __restrict__ ln1_b) {
    int idx = blockIdx.x * blockDim.x + threadIdx.x;
    if (idx >= L_ * CVP_) return;
    int e = idx % CVP_, l = idx / CVP_;
    int c = e >> 5, v = e & 31;
    float r = 0.f;
    if (v < V_) r = fmaxf(ln1_b[(l * C_ + c) * V_ + v], 0.f);
    g_aneg[l][e] = r;
}

// ---------------- input: LN over (CIN,V) + 1x1 conv --------------------------
__global__ void k_input(const float* __restrict__ x,
                        const float* __restrict__ lnw,
                        const float* __restrict__ lnb,
                        const float* __restrict__ Win,
                        const float* __restrict__ bin) {
    __shared__ float hn[CIN_ * V_];
    __shared__ float red[16];
    int t = blockIdx.x, tid = threadIdx.x;  // 128 threads

    float xv = 0.f, s = 0.f, ss = 0.f;
    if (tid < CIN_ * V_) {
        int ci = tid / V_, v = tid % V_;
        xv = x[(size_t)ci * T_ * V_ + (size_t)t * V_ + v];
        s = xv; ss = xv * xv;
    }
    #pragma unroll
    for (int o = 16; o; o >>= 1) {
        s  += __shfl_xor_sync(0xffffffffu, s, o);
        ss += __shfl_xor_sync(0xffffffffu, ss, o);
    }
    int wid = tid >> 5, lane = tid & 31;
    if (lane == 0) { red[wid] = s; red[4 + wid] = ss; }
    __syncthreads();
    if (tid == 0) {
        float S = red[0] + red[1] + red[2] + red[3];
        float SS = red[4] + red[5] + red[6] + red[7];
        float m = S / (CIN_ * V_);
        red[8] = m;
        red[9] = rsqrtf(SS / (CIN_ * V_) - m * m + 1e-5f);
    }
    __syncthreads();
    float m = red[8], rs = red[9];
    if (tid < CIN_ * V_) hn[tid] = (xv - m) * rs * lnw[tid] + lnb[tid];
    __syncthreads();

    float* out = g_h[0][t];
    for (int e = tid; e < CVP_; e += 128) {
        int c = e >> 5, v = e & 31;
        float a = 0.f;
        if (v < V_) {
            a = bin[c];
            #pragma unroll
            for (int ci = 0; ci < CIN_; ci++)
                a = fmaf(Win[c * CIN_ + ci], hn[ci * V_ + v], a);
        }
        out[e] = a;
    }
}

// ---------------- GCN: z = sum_k (Wg_k h) A_k + LN1 + relu -------------------
#define GCN_SMEM_FLOATS (CVP_ + K_*CVP_ + K_*V_*V_ + K_*V_ + 66)
__global__ __launch_bounds__(1024, 1)
void k_gcn(int l, int cur,
           const float* __restrict__ A,
           const float* __restrict__ imp,
           const float* __restrict__ bg,
           const float* __restrict__ ln1_w,
           const float* __restrict__ ln1_b) {
    extern __shared__ __align__(16) float sm[];
    float* h_s  = sm;                          // 8192 (stride-32 padded)
    float* hA_s = sm + CVP_;                   // 24576: [k][c][wp32]
    float* Al_s = sm + CVP_ + K_*CVP_;         // 1875
    float* rsum = Al_s + K_*V_*V_;             // 75
    float* red  = rsum + K_*V_;                // 66

    int t = blockIdx.x, tid = threadIdx.x;     // 1024 threads
    {
        const float4* src = (const float4*)g_h[cur][t];
        float4* dst = (float4*)h_s;
        #pragma unroll
        for (int i = 0; i < 2; i++) dst[tid + i * 1024] = src[tid + i * 1024];
    }
    for (int i = tid; i < K_ * V_ * V_; i += 1024)
        Al_s[i] = A[i] * imp[l * K_ * V_ * V_ + i];
    __syncthreads();

    for (int i = tid; i < K_ * V_; i += 1024) {
        int k = i / V_, w = i % V_;
        float s = 0.f;
        #pragma unroll
        for (int v = 0; v < V_; v++) s += Al_s[k * V_ * V_ + v * V_ + w];
        rsum[i] = s;
    }
    for (int e = tid; e < K_ * CV_; e += 1024) {
        int k = e / CV_, r = e % CV_, c = r / V_, w = r % V_;
        const float* hr = h_s + (c << 5);
        const float* ar = Al_s + k * V_ * V_ + w;
        float s = 0.f;
        #pragma unroll
        for (int v = 0; v < V_; v++) s = fmaf(hr[v], ar[v * V_], s);
        hA_s[k * CVP_ + (c << 5) + w] = s;
    }
    __syncthreads();

    // v-groups {8,8,8,1}
    int c = tid & 255, vg = tid >> 8;
    float acc[8];
    float s = 0.f, ss = 0.f;
    float bg0 = bg[l * K_ * C_ + c];
    float bg1 = bg[l * K_ * C_ + C_ + c];
    float bg2 = bg[l * K_ * C_ + 2 * C_ + c];

    if (vg < 3) {
        int vb = vg << 3;
        #pragma unroll
        for (int j = 0; j < 8; j++) {
            int w = vb + j;
            acc[j] = bg0 * rsum[w] + bg1 * rsum[V_ + w] + bg2 * rsum[2 * V_ + w];
        }
        #pragma unroll
        for (int k = 0; k < K_; k++) {
            const float* wg = &g_WgT[l][k][0][c];
            const float* ap = hA_s + k * CVP_ + vb;
            #pragma unroll 4
            for (int ci = 0; ci < C_; ci++) {
                float wv = wg[ci * C_];
                float4 h0 = *(const float4*)(ap + (ci << 5));
                float4 h1 = *(const float4*)(ap + (ci << 5) + 4);
                acc[0] = fmaf(wv, h0.x, acc[0]);
                acc[1] = fmaf(wv, h0.y, acc[1]);
                acc[2] = fmaf(wv, h0.z, acc[2]);
                acc[3] = fmaf(wv, h0.w, acc[3]);
                acc[4] = fmaf(wv, h1.x, acc[4]);
                acc[5] = fmaf(wv, h1.y, acc[5]);
                acc[6] = fmaf(wv, h1.z, acc[6]);
                acc[7] = fmaf(wv, h1.w, acc[7]);
            }
        }
        #pragma unroll
        for (int j = 0; j < 8; j++) { s += acc[j]; ss += acc[j] * acc[j]; }
    } else {
        acc[0] = bg0 * rsum[24] + bg1 * rsum[V_ + 24] + bg2 * rsum[2 * V_ + 24];
        #pragma unroll
        for (int k = 0; k < K_; k++) {
            const float* wg = &g_WgT[l][k][0][c];
            const float* ap = hA_s + k * CVP_ + 24;
            #pragma unroll 4
            for (int ci = 0; ci < C_; ci++)
                acc[0] = fmaf(wg[ci * C_], ap[ci << 5], acc[0]);
        }
        s = acc[0]; ss = acc[0] * acc[0];
    }

    #pragma unroll
    for (int o = 16; o; o >>= 1) {
        s  += __shfl_xor_sync(0xffffffffu, s, o);
        ss += __shfl_xor_sync(0xffffffffu, ss, o);
    }
    int wid = tid >> 5, lane = tid & 31;
    if (lane == 0) { red[wid] = s; red[32 + wid] = ss; }
    __syncthreads();
    if (tid < 32) {
        float S = red[tid], SS = red[32 + tid];
        #pragma unroll
        for (int o = 16; o; o >>= 1) {
            S  += __shfl_xor_sync(0xffffffffu, S, o);
            SS += __shfl_xor_sync(0xffffffffu, SS, o);
        }
        if (tid == 0) {
            float m = S / CV_;
            red[64] = m;
            red[65] = rsqrtf(SS / CV_ - m * m + 1e-5f);
        }
    }
    __syncthreads();
    float m = red[64], rs = red[65];

    const float* w1 = ln1_w + (l * C_ + c) * V_;
    const float* b1 = ln1_b + (l * C_ + c) * V_;
    float* outp = g_anorm[t] + (c << 5);
    if (vg < 3) {
        int vb = vg << 3;
        #pragma unroll
        for (int j = 0; j < 8; j++) {
            int v = vb + j;
            outp[v] = fmaxf(fmaf((acc[j] - m) * rs, w1[v], b1[v]), 0.f);
        }
    } else {
        outp[24] = fmaxf(fmaf((acc[0] - m) * rs, w1[24], b1[24]), 0.f);
    }
}

// ---------------- TCN via mma.sync (bf16 hi/lo split) ------------------------
// B staged per-g into smem: [v][ci-pair] swizzled word = v*132 + ((p+v)&127)
__global__ __launch_bounds__(1024, 1)
void k_tcn(int l, int cur,
           const float* __restrict__ bt,
           const float* __restrict__ ln2_w,
           const float* __restrict__ ln2_b) {
    __shared__ unsigned sB[2 * 32 * 132];   // hi @0, lo @4224 (words)
    __shared__ float red[66];
    int t = blockIdx.x, tid = threadIdx.x;  // 1024 threads
    int wid = tid >> 5, lane = tid & 31;
    int grp = lane >> 2, tig = lane & 3;
    int mt = wid >> 1, nhalf = wid & 1;

    float d0[4] = {0.f, 0.f, 0.f, 0.f};
    float d1[4] = {0.f, 0.f, 0.f, 0.f};

    int sv = tid & 31;                 // staging v
    int cb = (tid >> 5) << 3;          // staging channel base (8 channels)

    for (int g = 0; g < G_; g++) {
        int tau = t - g;
        const float* src = (tau >= 0) ? g_anorm[tau] : g_aneg[l];
        __syncthreads();   // previous mma reads done before overwrite
        #pragma unroll
        for (int j = 0; j < 4; j++) {
            int c0 = cb + 2 * j;
            float x0 = src[(c0 << 5) + sv];
            float x1 = src[((c0 + 1) << 5) + sv];
            unsigned short h0 = f2bf(x0), h1 = f2bf(x1);
            unsigned short q0 = f2bf(x0 - bf2f(h0)), q1 = f2bf(x1 - bf2f(h1));
            int p = c0 >> 1;
            int w = sv * 132 + ((p + sv) & 127);
            sB[w]        = (unsigned)h0 | ((unsigned)h1 << 16);
            sB[4224 + w] = (unsigned)q0 | ((unsigned)q1 << 16);
        }
        __syncthreads();

        const uint4* aH = g_WtPk + ((size_t)((l * 9 + g) * 2) * 16 + mt) * 512 + lane;
        const uint4* aL = aH + 8192;
        #pragma unroll 2
        for (int kt = 0; kt < 16; kt++) {
            uint4 ah = aH[kt * 32];
            uint4 al = aL[kt * 32];
            int kb2 = kt * 8;
            {   // n-tile pair 0
                int vr = (nhalf * 2) * 8 + grp;
                int rb = vr * 132;
                int w0 = rb + ((kb2 + tig + vr) & 127);
                int w1 = rb + ((kb2 + 4 + tig + vr) & 127);
                unsigned bh0 = sB[w0], bh1 = sB[w1];
                unsigned bl0 = sB[4224 + w0], bl1 = sB[4224 + w1];
                MMA16816(d0, ah, bh0, bh1);
                MMA16816(d0, ah, bl0, bl1);
                MMA16816(d0, al, bh0, bh1);
            }
            {   // n-tile pair 1
                int vr = (nhalf * 2 + 1) * 8 + grp;
                int rb = vr * 132;
                int w0 = rb + ((kb2 + tig + vr) & 127);
                int w1 = rb + ((kb2 + 4 + tig + vr) & 127);
                unsigned bh0 = sB[w0], bh1 = sB[w1];
                unsigned bl0 = sB[4224 + w0], bl1 = sB[4224 + w1];
                MMA16816(d1, ah, bh0, bh1);
                MMA16816(d1, ah, bl0, bl1);
                MMA16816(d1, al, bh0, bh1);
            }
        }
    }

    // ---- epilogue: bias + LN2 stats + residual + relu ----
    float vals[2][4];
    float s = 0.f, ss = 0.f;
    #pragma unroll
    for (int p2 = 0; p2 < 2; p2++) {
        float* dd = p2 ? d1 : d0;
        #pragma unroll
        for (int r = 0; r < 4; r++) {
            int o = mt * 16 + grp + ((r >> 1) << 3);
            int v = (nhalf * 2 + p2) * 8 + tig * 2 + (r & 1);
            float xx = dd[r] + bt[l * C_ + o];
            vals[p2][r] = xx;
            if (v < V_) { s += xx; ss += xx * xx; }
        }
    }
    #pragma unroll
    for (int off = 16; off; off >>= 1) {
        s  += __shfl_xor_sync(0xffffffffu, s, off);
        ss += __shfl_xor_sync(0xffffffffu, ss, off);
    }
    if (lane == 0) { red[wid] = s; red[32 + wid] = ss; }
    __syncthreads();
    if (tid < 32) {
        float S = red[tid], SS = red[32 + tid];
        #pragma unroll
        for (int off = 16; off; off >>= 1) {
            S  += __shfl_xor_sync(0xffffffffu, S, off);
            SS += __shfl_xor_sync(0xffffffffu, SS, off);
        }
        if (tid == 0) {
            float m = S / CV_;
            red[64] = m;
            red[65] = rsqrtf(SS / CV_ - m * m + 1e-5f);
        }
    }
    __syncthreads();
    float m = red[64], rs = red[65];

    const float* resp = (t >= GH_) ? g_h[cur][t - GH_] : nullptr;
    float* outp = g_h[cur ^ 1][t];
    #pragma unroll
    for (int p2 = 0; p2 < 2; p2++) {
        #pragma unroll
        for (int r = 0; r < 4; r++) {
            int o = mt * 16 + grp + ((r >> 1) << 3);
            int v = (nhalf * 2 + p2) * 8 + tig * 2 + (r & 1);
            if (v < V_) {
                float res = resp ? resp[(o << 5) + v] : 0.f;
                float w2 = ln2_w[(l * C_ + o) * V_ + v];
                float b2 = ln2_b[(l * C_ + o) * V_ + v];
                outp[(o << 5) + v] =
                    fmaxf(fmaf((vals[p2][r] - m) * rs, w2, b2) + res, 0.f);
            }
        }
    }
}

// ---------------- head: mean over V + linear ---------------------------------
__global__ void k_out(int cur,
                      const float* __restrict__ Wout,
                      const float* __restrict__ bout,
                      float* __restrict__ out) {
    __shared__ float pooled[C_];
    int t = blockIdx.x, tid = threadIdx.x;  // 256
    const float* h = g_h[cur][t];
    float s = 0.f;
    #pragma unroll
    for (int v = 0; v < V_; v++) s += h[(tid << 5) + v];
    pooled[tid] = s * (1.f / V_);
    __syncthreads();
    if (tid < NC_) {
        float a = bout[tid];
        #pragma unroll 8
        for (int c = 0; c < C_; c++) a = fmaf(Wout[tid * C_ + c], pooled[c], a);
        out[t * NC_ + tid] = a;
    }
}

// ---------------- launch ------------------------------------------------------
extern "C" void kernel_launch(void* const* d_in, const int* in_sizes, int n_in,
                              void* d_out, int out_size) {
    const float* x       = (const float*)d_in[0];
    const float* A       = (const float*)d_in[1];
    const float* ln_in_w = (const float*)d_in[2];
    const float* ln_in_b = (const float*)d_in[3];
    const float* W_in    = (const float*)d_in[4];
    const float* b_in    = (const float*)d_in[5];
    const float* Wg      = (const float*)d_in[6];
    const float* bg      = (const float*)d_in[7];
    const float* ln1_w   = (const float*)d_in[8];
    const float* ln1_b   = (const float*)d_in[9];
    const float* Wt      = (const float*)d_in[10];
    const float* bt      = (const float*)d_in[11];
    const float* ln2_w   = (const float*)d_in[12];
    const float* ln2_b   = (const float*)d_in[13];
    const float* imp     = (const float*)d_in[14];
    const float* W_out   = (const float*)d_in[15];
    const float* b_out   = (const float*)d_in[16];
    float* out = (float*)d_out;

    int gcn_smem = GCN_SMEM_FLOATS * (int)sizeof(float);
    cudaFuncSetAttribute(k_gcn, cudaFuncAttributeMaxDynamicSharedMemorySize, gcn_smem);

    {
        int n = L_ * K_ * C_ * C_;
        k_prep_wg<<<(n + 255) / 256, 256>>>(Wg);
    }
    {
        int n = L_ * G_ * 2 * 16 * 16 * 32;
        k_prep_wtpk<<<(n + 255) / 256, 256>>>(Wt);
    }
    {
        int n = L_ * CVP_;
        k_prep_aneg<<<(n + 255) / 256, 256>>>(ln1_b);
    }
    k_input<<<T_, 128>>>(x, ln_in_w, ln_in_b, W_in, b_in);

    int cur = 0;
    for (int l = 0; l < L_; l++) {
        k_gcn<<<T_, 1024, gcn_smem>>>(l, cur, A, imp, bg, ln1_w, ln1_b);
        k_tcn<<<T_, 1024>>>(l, cur, bt, ln2_w, ln2_b);
        cur ^= 1;
    }
    k_out<<<T_, 256>>>(cur, W_out, b_out, out);
}